// round 15
// baseline (speedup 1.0000x reference)
#include <cuda_runtime.h>
#include <cuda_fp16.h>
#include <cuda_bf16.h>

#define NN 50000
#define EE 1600000
#define HD 128
#define MAXDEG 128    // bucket capacity; max degree ~62 for Poisson(32)
#define ASTRIDE 136   // halves per smem row (272B: 16B-aligned, conflict-free)

typedef unsigned long long ull;

// ---------------- scratch (static device globals; no allocation) ------------
__device__ __half g_xl16[NN * HD];        // fp16 mirror of xl (gathered per edge)
__device__ __half g_xr16[NN * HD];        // fp16 mirror of xr (logit side)
__device__ int    g_cnt[NN];              // per-node degree (incl. self loop)
__device__ int    g_psrc[NN * MAXDEG];    // padded per-node source buckets

__device__ __forceinline__ unsigned smem_u32(const void* p) {
    unsigned a;
    asm("{ .reg .u64 t; cvta.to.shared.u64 t, %1; cvt.u32.u64 %0, t; }"
        : "=r"(a) : "l"(p));
    return a;
}

// ---------------- tensor-core dual GEMM (mma.sync m16n8k16 fp16->fp32) ------
__global__ void __launch_bounds__(256, 2)
gemm_mma_kernel(const float* __restrict__ x,
                const float* __restrict__ Wl, const float* __restrict__ bl,
                const float* __restrict__ Wr, const float* __restrict__ br,
                int n) {
    extern __shared__ __half smh[];
    __half* As = smh;                       // [128][ASTRIDE]
    __half* Bs = smh + 128 * ASTRIDE;       // [128][ASTRIDE]
    __shared__ float sbias[HD];

    const float* W    = blockIdx.y ? Wr : Wl;
    const float* bvec = blockIdx.y ? br : bl;
    __half* outh      = blockIdx.y ? g_xr16 : g_xl16;

    int tid  = threadIdx.x;
    int lane = tid & 31;
    int w    = tid >> 5;
    int row0 = blockIdx.x * 128;

    for (int idx = tid; idx < 128 * 32; idx += 256) {
        int r = idx >> 5, c4 = idx & 31;
        int row = row0 + r;
        float4 v = make_float4(0.f, 0.f, 0.f, 0.f);
        if (row < n) v = ((const float4*)x)[row * 32 + c4];
        __half2 p0 = __floats2half2_rn(v.x, v.y);
        __half2 p1 = __floats2half2_rn(v.z, v.w);
        *(__half2*)&As[r * ASTRIDE + c4 * 4]     = p0;
        *(__half2*)&As[r * ASTRIDE + c4 * 4 + 2] = p1;
    }
    for (int idx = tid; idx < 128 * 32; idx += 256) {
        int r = idx >> 5, c4 = idx & 31;
        float4 v = ((const float4*)W)[r * 32 + c4];
        __half2 p0 = __floats2half2_rn(v.x, v.y);
        __half2 p1 = __floats2half2_rn(v.z, v.w);
        *(__half2*)&Bs[r * ASTRIDE + c4 * 4]     = p0;
        *(__half2*)&Bs[r * ASTRIDE + c4 * 4 + 2] = p1;
    }
    if (tid < HD) sbias[tid] = bvec[tid];
    __syncthreads();

    float acc[16][4];
#pragma unroll
    for (int f = 0; f < 16; f++)
#pragma unroll
        for (int t = 0; t < 4; t++) acc[f][t] = 0.0f;

    int rw = w * 16;
    int a_row = rw + (lane & 15);
    int a_coff = (lane >> 4) << 3;
    int b_roff = lane & 15;

#pragma unroll
    for (int ks = 0; ks < 8; ks++) {
        int kb = ks * 16;
        unsigned addrA = smem_u32(&As[a_row * ASTRIDE + kb + a_coff]);
        unsigned a0, a1, a2, a3;
        asm volatile("ldmatrix.sync.aligned.m8n8.x4.shared.b16 {%0,%1,%2,%3}, [%4];"
                     : "=r"(a0), "=r"(a1), "=r"(a2), "=r"(a3) : "r"(addrA));
#pragma unroll
        for (int nf = 0; nf < 16; nf++) {
            int nb = nf * 8;
            unsigned addrB = smem_u32(&Bs[(kb + b_roff) * ASTRIDE + nb]);
            unsigned b0, b1;
            asm volatile("ldmatrix.sync.aligned.m8n8.x2.trans.shared.b16 {%0,%1}, [%2];"
                         : "=r"(b0), "=r"(b1) : "r"(addrB));
            asm volatile("mma.sync.aligned.m16n8k16.row.col.f32.f16.f16.f32 "
                         "{%0,%1,%2,%3}, {%4,%5,%6,%7}, {%8,%9}, {%0,%1,%2,%3};"
                         : "+f"(acc[nf][0]), "+f"(acc[nf][1]),
                           "+f"(acc[nf][2]), "+f"(acc[nf][3])
                         : "r"(a0), "r"(a1), "r"(a2), "r"(a3), "r"(b0), "r"(b1));
        }
    }

    int r0 = row0 + rw + (lane >> 2);
    int r1 = r0 + 8;
#pragma unroll
    for (int nf = 0; nf < 16; nf++) {
        int c = nf * 8 + (lane & 3) * 2;
        float bx = sbias[c], by = sbias[c + 1];
        if (r0 < n)
            *(__half2*)&outh[r0 * HD + c] = __floats2half2_rn(acc[nf][0] + bx, acc[nf][1] + by);
        if (r1 < n)
            *(__half2*)&outh[r1 * HD + c] = __floats2half2_rn(acc[nf][2] + bx, acc[nf][3] + by);
    }
}

// ---------------- bucket CSR: init (self loop) + single atomic fill ----------
__global__ void init_buckets_kernel(int n) {
    int i = blockIdx.x * blockDim.x + threadIdx.x;
    if (i < n) {
        g_cnt[i] = 1;                 // self loop occupies slot 0
        g_psrc[i << 7] = i;
    }
}

__global__ void fill_kernel(const int* __restrict__ src, const int* __restrict__ dst,
                            int E) {
    int base = (blockIdx.x * blockDim.x + threadIdx.x) * 8;
    if (base + 7 < E) {
        int4 s0 = *(const int4*)(src + base);
        int4 s1 = *(const int4*)(src + base + 4);
        int4 d0 = *(const int4*)(dst + base);
        int4 d1 = *(const int4*)(dst + base + 4);
        int p0 = atomicAdd(&g_cnt[d0.x], 1);
        int p1 = atomicAdd(&g_cnt[d0.y], 1);
        int p2 = atomicAdd(&g_cnt[d0.z], 1);
        int p3 = atomicAdd(&g_cnt[d0.w], 1);
        int p4 = atomicAdd(&g_cnt[d1.x], 1);
        int p5 = atomicAdd(&g_cnt[d1.y], 1);
        int p6 = atomicAdd(&g_cnt[d1.z], 1);
        int p7 = atomicAdd(&g_cnt[d1.w], 1);
        g_psrc[(d0.x << 7) + p0] = s0.x;
        g_psrc[(d0.y << 7) + p1] = s0.y;
        g_psrc[(d0.z << 7) + p2] = s0.z;
        g_psrc[(d0.w << 7) + p3] = s0.w;
        g_psrc[(d1.x << 7) + p4] = s1.x;
        g_psrc[(d1.y << 7) + p5] = s1.y;
        g_psrc[(d1.z << 7) + p6] = s1.z;
        g_psrc[(d1.w << 7) + p7] = s1.w;
    } else {
        for (int i = base; i < E; i++) {
            int d = dst[i];
            int pos = atomicAdd(&g_cnt[d], 1);
            g_psrc[(d << 7) + pos] = src[i];
        }
    }
}

// ---------------- main fused GATv2 kernel: one warp per node, 2 edges/pass ---
// (R10/R13-verified structure) 16 lanes/edge; lane (eslot*16+q) owns ch 8q..8q+7.
__device__ __forceinline__ float edge_logit(uint4 raw,
                                            const __half2* xrh,
                                            const __half2* a6,
                                            const __half2* a4) {
    __half2 h0 = *(__half2*)&raw.x, h1 = *(__half2*)&raw.y;
    __half2 h2 = *(__half2*)&raw.z, h3 = *(__half2*)&raw.w;
    __half2 m0 = __hadd2(h0, xrh[0]);
    __half2 m1 = __hadd2(h1, xrh[1]);
    __half2 m2 = __hadd2(h2, xrh[2]);
    __half2 m3 = __hadd2(h3, xrh[3]);
    unsigned b0 = (*(unsigned*)&m0) & 0x7FFF7FFFu;   // |m| on the ALU pipe
    unsigned b1 = (*(unsigned*)&m1) & 0x7FFF7FFFu;
    unsigned b2 = (*(unsigned*)&m2) & 0x7FFF7FFFu;
    unsigned b3 = (*(unsigned*)&m3) & 0x7FFF7FFFu;
    __half2 t0 = __hmul2(a4[0], *(__half2*)&b0);
    t0 = __hfma2(a6[0], m0, t0);
    t0 = __hfma2(a4[1], *(__half2*)&b1, t0);
    t0 = __hfma2(a6[1], m1, t0);
    __half2 t1 = __hmul2(a4[2], *(__half2*)&b2);
    t1 = __hfma2(a6[2], m2, t1);
    t1 = __hfma2(a4[3], *(__half2*)&b3, t1);
    t1 = __hfma2(a6[3], m3, t1);
    float2 tf = __half22float2(__hadd2(t0, t1));
    return tf.x + tf.y;
}

__device__ __forceinline__ void edge_acc(uint4 raw, float ex, float* acc) {
    float2 f;
    f = __half22float2(*(__half2*)&raw.x);
    acc[0] = fmaf(ex, f.x, acc[0]);
    acc[1] = fmaf(ex, f.y, acc[1]);
    f = __half22float2(*(__half2*)&raw.y);
    acc[2] = fmaf(ex, f.x, acc[2]);
    acc[3] = fmaf(ex, f.y, acc[3]);
    f = __half22float2(*(__half2*)&raw.z);
    acc[4] = fmaf(ex, f.x, acc[4]);
    acc[5] = fmaf(ex, f.y, acc[5]);
    f = __half22float2(*(__half2*)&raw.w);
    acc[6] = fmaf(ex, f.x, acc[6]);
    acc[7] = fmaf(ex, f.y, acc[7]);
}

__global__ void __launch_bounds__(256, 6)
gat_main_kernel(const float* __restrict__ att,
                const float* __restrict__ bias,
                const int* __restrict__ batch,
                float* __restrict__ pooled, int n) {
    __shared__ int pbuf[HD];
    __shared__ int bmn, bmx;
    int tid = threadIdx.x;
    if (tid < HD) pbuf[tid] = 0;
    if (tid == 0) { bmn = 1 << 30; bmx = -1; }
    __syncthreads();

    int gw    = (blockIdx.x * blockDim.x + tid) >> 5;
    int lane  = tid & 31;
    int q     = lane & 15;      // channel-group: ch 8q..8q+7
    int eslot = lane >> 4;      // which edge of the pair
    bool active = (gw < n);
    float o[8] = {0, 0, 0, 0, 0, 0, 0, 0};
    int b = 0;

    if (active) {
        int i = gw;
        uint4 xr_raw = __ldg((const uint4*)g_xr16 + i * 16 + q);
        __half2 xrh[4] = { *(__half2*)&xr_raw.x, *(__half2*)&xr_raw.y,
                           *(__half2*)&xr_raw.z, *(__half2*)&xr_raw.w };
        float4 avA = ((const float4*)att)[q * 2];
        float4 avB = ((const float4*)att)[q * 2 + 1];
        __half2 a6[4] = { __floats2half2_rn(0.6f * avA.x, 0.6f * avA.y),
                          __floats2half2_rn(0.6f * avA.z, 0.6f * avA.w),
                          __floats2half2_rn(0.6f * avB.x, 0.6f * avB.y),
                          __floats2half2_rn(0.6f * avB.z, 0.6f * avB.w) };
        __half2 a4[4] = { __floats2half2_rn(0.4f * avA.x, 0.4f * avA.y),
                          __floats2half2_rn(0.4f * avA.z, 0.4f * avA.w),
                          __floats2half2_rn(0.4f * avB.x, 0.4f * avB.y),
                          __floats2half2_rn(0.4f * avB.z, 0.4f * avB.w) };

        float acc[8] = {0, 0, 0, 0, 0, 0, 0, 0};
        float den = 0.0f;

        int s0 = i << 7;                    // bucket base
        int s1 = s0 + g_cnt[i];             // bucket end (deg incl. self loop)
        int base = s0;
        for (; base + 4 <= s1; base += 4) {          // 4 edges, 2 LDG.128 in flight
            int j0 = __ldg(&g_psrc[base + eslot]);
            int j1 = __ldg(&g_psrc[base + 2 + eslot]);
            uint4 r0 = __ldg((const uint4*)g_xl16 + j0 * 16 + q);
            uint4 r1 = __ldg((const uint4*)g_xl16 + j1 * 16 + q);

            float sA = edge_logit(r0, xrh, a6, a4);
            float sB = edge_logit(r1, xrh, a6, a4);
            sA += __shfl_xor_sync(0xFFFFFFFFu, sA, 1);
            sB += __shfl_xor_sync(0xFFFFFFFFu, sB, 1);
            sA += __shfl_xor_sync(0xFFFFFFFFu, sA, 2);
            sB += __shfl_xor_sync(0xFFFFFFFFu, sB, 2);

            float eA = __expf(sA);
            float eB = __expf(sB);
            den += eA + eB;
            edge_acc(r0, eA, acc);
            edge_acc(r1, eB, acc);
        }
        for (; base < s1; base += 2) {               // masked tail pair
            int ei = base + eslot;
            int j = __ldg(&g_psrc[(ei < s1) ? ei : (s1 - 1)]);
            uint4 r = __ldg((const uint4*)g_xl16 + j * 16 + q);
            float s = edge_logit(r, xrh, a6, a4);
            s += __shfl_xor_sync(0xFFFFFFFFu, s, 1);
            s += __shfl_xor_sync(0xFFFFFFFFu, s, 2);
            float ex = (ei < s1) ? __expf(s) : 0.0f;
            den += ex;
            edge_acc(r, ex, acc);
        }

        // merge the two 16-lane halves (per-head den, per-channel acc)
        den += __shfl_xor_sync(0xFFFFFFFFu, den, 16);
#pragma unroll
        for (int t = 0; t < 8; t++)
            acc[t] += __shfl_xor_sync(0xFFFFFFFFu, acc[t], 16);

        float inv = 1.0f / den;
        float4 bvA = ((const float4*)bias)[q * 2];
        float4 bvB = ((const float4*)bias)[q * 2 + 1];
        o[0] = fmaxf(fmaf(acc[0], inv, bvA.x), 0.0f);
        o[1] = fmaxf(fmaf(acc[1], inv, bvA.y), 0.0f);
        o[2] = fmaxf(fmaf(acc[2], inv, bvA.z), 0.0f);
        o[3] = fmaxf(fmaf(acc[3], inv, bvA.w), 0.0f);
        o[4] = fmaxf(fmaf(acc[4], inv, bvB.x), 0.0f);
        o[5] = fmaxf(fmaf(acc[5], inv, bvB.y), 0.0f);
        o[6] = fmaxf(fmaf(acc[6], inv, bvB.z), 0.0f);
        o[7] = fmaxf(fmaf(acc[7], inv, bvB.w), 0.0f);

        b = batch[i];
        if (lane == 0) { atomicMin(&bmn, b); atomicMax(&bmx, b); }
    }
    __syncthreads();

    if (bmn == bmx) {
        if (active && eslot == 0) {
#pragma unroll
            for (int t = 0; t < 8; t++)
                atomicMax(&pbuf[q * 8 + t], __float_as_int(o[t]));
        }
        __syncthreads();
        if (tid < HD && bmx >= 0)
            atomicMax((int*)pooled + bmx * HD + tid, pbuf[tid]);
    } else if (active && eslot == 0) {
        int* pp = (int*)pooled + b * HD + q * 8;
#pragma unroll
        for (int t = 0; t < 8; t++)
            atomicMax(pp + t, __float_as_int(o[t]));
    }
}

// ---------------- launcher ---------------------------------------------------
extern "C" void kernel_launch(void* const* d_in, const int* in_sizes, int n_in,
                              void* d_out, int out_size) {
    const float* x    = (const float*)d_in[0];
    const int*   ei   = (const int*)d_in[1];
    const int*   batch= (const int*)d_in[2];
    const float* Wl   = (const float*)d_in[3];
    const float* bl   = (const float*)d_in[4];
    const float* Wr   = (const float*)d_in[5];
    const float* br   = (const float*)d_in[6];
    const float* att  = (const float*)d_in[7];
    const float* bias = (const float*)d_in[8];
    float* out = (float*)d_out;

    int n = in_sizes[2];          // nodes
    int E = in_sizes[1] / 2;      // edges
    const int* esrc = ei;
    const int* edst = ei + E;

    static cudaStream_t s2 = nullptr;
    static cudaEvent_t eFork = nullptr, eJoin = nullptr;
    if (s2 == nullptr) {
        cudaStreamCreateWithFlags(&s2, cudaStreamNonBlocking);
        cudaEventCreateWithFlags(&eFork, cudaEventDisableTiming);
        cudaEventCreateWithFlags(&eJoin, cudaEventDisableTiming);
    }

    int gemm_smem = 2 * 128 * ASTRIDE * (int)sizeof(__half);   // ~68 KB
    cudaFuncSetAttribute(gemm_mma_kernel,
                         cudaFuncAttributeMaxDynamicSharedMemorySize, gemm_smem);

    // fork: bucket build on s2, GEMM on the captured (default) stream
    cudaEventRecord(eFork, 0);
    cudaStreamWaitEvent(s2, eFork, 0);

    int e8 = (E + 7) / 8;
    init_buckets_kernel<<<(n + 255) / 256, 256, 0, s2>>>(n);
    fill_kernel<<<(e8 + 255) / 256, 256, 0, s2>>>(esrc, edst, E);
    cudaEventRecord(eJoin, s2);

    cudaMemsetAsync(out, 0, (size_t)out_size * sizeof(float), 0);
    dim3 ggrid((n + 127) / 128, 2);
    gemm_mma_kernel<<<ggrid, 256, gemm_smem>>>(x, Wl, bl, Wr, br, n);

    // join, then fused GATv2 + pool
    cudaStreamWaitEvent(0, eJoin, 0);
    gat_main_kernel<<<(n * 32 + 255) / 256, 256>>>(att, bias, batch, out, n);
}

// round 16
// speedup vs baseline: 1.0761x; 1.0761x over previous
#include <cuda_runtime.h>
#include <cuda_fp16.h>
#include <cuda_bf16.h>

#define NN 50000
#define EE 1600000
#define HD 128
#define MAXDEG 128    // bucket capacity; max degree ~62 for Poisson(32)
#define ASTRIDE 136   // halves per smem row (272B: 16B-aligned, conflict-free)

typedef unsigned long long ull;

// ---------------- scratch (static device globals; no allocation) ------------
__device__ __half g_xl16[NN * HD];        // fp16 mirror of xl (gathered per edge)
__device__ __half g_xr16[NN * HD];        // fp16 mirror of xr (logit side)
__device__ int    g_cnt[NN];              // per-node degree (incl. self loop)
__device__ int    g_psrc[NN * MAXDEG];    // padded per-node source buckets

__device__ __forceinline__ unsigned smem_u32(const void* p) {
    unsigned a;
    asm("{ .reg .u64 t; cvta.to.shared.u64 t, %1; cvt.u32.u64 %0, t; }"
        : "=r"(a) : "l"(p));
    return a;
}

// ---------------- tensor-core dual GEMM (mma.sync m16n8k16 fp16->fp32) ------
__global__ void __launch_bounds__(256, 2)
gemm_mma_kernel(const float* __restrict__ x,
                const float* __restrict__ Wl, const float* __restrict__ bl,
                const float* __restrict__ Wr, const float* __restrict__ br,
                int n) {
    extern __shared__ __half smh[];
    __half* As = smh;                       // [128][ASTRIDE]
    __half* Bs = smh + 128 * ASTRIDE;       // [128][ASTRIDE]
    __shared__ float sbias[HD];

    const float* W    = blockIdx.y ? Wr : Wl;
    const float* bvec = blockIdx.y ? br : bl;
    __half* outh      = blockIdx.y ? g_xr16 : g_xl16;

    int tid  = threadIdx.x;
    int lane = tid & 31;
    int w    = tid >> 5;
    int row0 = blockIdx.x * 128;

    for (int idx = tid; idx < 128 * 32; idx += 256) {
        int r = idx >> 5, c4 = idx & 31;
        int row = row0 + r;
        float4 v = make_float4(0.f, 0.f, 0.f, 0.f);
        if (row < n) v = ((const float4*)x)[row * 32 + c4];
        __half2 p0 = __floats2half2_rn(v.x, v.y);
        __half2 p1 = __floats2half2_rn(v.z, v.w);
        *(__half2*)&As[r * ASTRIDE + c4 * 4]     = p0;
        *(__half2*)&As[r * ASTRIDE + c4 * 4 + 2] = p1;
    }
    for (int idx = tid; idx < 128 * 32; idx += 256) {
        int r = idx >> 5, c4 = idx & 31;
        float4 v = ((const float4*)W)[r * 32 + c4];
        __half2 p0 = __floats2half2_rn(v.x, v.y);
        __half2 p1 = __floats2half2_rn(v.z, v.w);
        *(__half2*)&Bs[r * ASTRIDE + c4 * 4]     = p0;
        *(__half2*)&Bs[r * ASTRIDE + c4 * 4 + 2] = p1;
    }
    if (tid < HD) sbias[tid] = bvec[tid];
    __syncthreads();

    float acc[16][4];
#pragma unroll
    for (int f = 0; f < 16; f++)
#pragma unroll
        for (int t = 0; t < 4; t++) acc[f][t] = 0.0f;

    int rw = w * 16;
    int a_row = rw + (lane & 15);
    int a_coff = (lane >> 4) << 3;
    int b_roff = lane & 15;

#pragma unroll
    for (int ks = 0; ks < 8; ks++) {
        int kb = ks * 16;
        unsigned addrA = smem_u32(&As[a_row * ASTRIDE + kb + a_coff]);
        unsigned a0, a1, a2, a3;
        asm volatile("ldmatrix.sync.aligned.m8n8.x4.shared.b16 {%0,%1,%2,%3}, [%4];"
                     : "=r"(a0), "=r"(a1), "=r"(a2), "=r"(a3) : "r"(addrA));
#pragma unroll
        for (int nf = 0; nf < 16; nf++) {
            int nb = nf * 8;
            unsigned addrB = smem_u32(&Bs[(kb + b_roff) * ASTRIDE + nb]);
            unsigned b0, b1;
            asm volatile("ldmatrix.sync.aligned.m8n8.x2.trans.shared.b16 {%0,%1}, [%2];"
                         : "=r"(b0), "=r"(b1) : "r"(addrB));
            asm volatile("mma.sync.aligned.m16n8k16.row.col.f32.f16.f16.f32 "
                         "{%0,%1,%2,%3}, {%4,%5,%6,%7}, {%8,%9}, {%0,%1,%2,%3};"
                         : "+f"(acc[nf][0]), "+f"(acc[nf][1]),
                           "+f"(acc[nf][2]), "+f"(acc[nf][3])
                         : "r"(a0), "r"(a1), "r"(a2), "r"(a3), "r"(b0), "r"(b1));
        }
    }

    int r0 = row0 + rw + (lane >> 2);
    int r1 = r0 + 8;
#pragma unroll
    for (int nf = 0; nf < 16; nf++) {
        int c = nf * 8 + (lane & 3) * 2;
        float bx = sbias[c], by = sbias[c + 1];
        if (r0 < n)
            *(__half2*)&outh[r0 * HD + c] = __floats2half2_rn(acc[nf][0] + bx, acc[nf][1] + by);
        if (r1 < n)
            *(__half2*)&outh[r1 * HD + c] = __floats2half2_rn(acc[nf][2] + bx, acc[nf][3] + by);
    }
}

// ---------------- bucket CSR: init (self loop) + single atomic fill ----------
__global__ void init_buckets_kernel(int n) {
    int i = blockIdx.x * blockDim.x + threadIdx.x;
    if (i < n) {
        g_cnt[i] = 1;                 // self loop occupies slot 0
        g_psrc[i << 7] = i;
    }
}

__global__ void fill_kernel(const int* __restrict__ src, const int* __restrict__ dst,
                            int E) {
    int base = (blockIdx.x * blockDim.x + threadIdx.x) * 8;
    if (base + 7 < E) {
        int4 s0 = *(const int4*)(src + base);
        int4 s1 = *(const int4*)(src + base + 4);
        int4 d0 = *(const int4*)(dst + base);
        int4 d1 = *(const int4*)(dst + base + 4);
        int p0 = atomicAdd(&g_cnt[d0.x], 1);
        int p1 = atomicAdd(&g_cnt[d0.y], 1);
        int p2 = atomicAdd(&g_cnt[d0.z], 1);
        int p3 = atomicAdd(&g_cnt[d0.w], 1);
        int p4 = atomicAdd(&g_cnt[d1.x], 1);
        int p5 = atomicAdd(&g_cnt[d1.y], 1);
        int p6 = atomicAdd(&g_cnt[d1.z], 1);
        int p7 = atomicAdd(&g_cnt[d1.w], 1);
        g_psrc[(d0.x << 7) + p0] = s0.x;
        g_psrc[(d0.y << 7) + p1] = s0.y;
        g_psrc[(d0.z << 7) + p2] = s0.z;
        g_psrc[(d0.w << 7) + p3] = s0.w;
        g_psrc[(d1.x << 7) + p4] = s1.x;
        g_psrc[(d1.y << 7) + p5] = s1.y;
        g_psrc[(d1.z << 7) + p6] = s1.z;
        g_psrc[(d1.w << 7) + p7] = s1.w;
    } else {
        for (int i = base; i < E; i++) {
            int d = dst[i];
            int pos = atomicAdd(&g_cnt[d], 1);
            g_psrc[(d << 7) + pos] = src[i];
        }
    }
}

// ---------------- main fused GATv2 kernel: one warp per node, 2 edges/pass ---
// 16 lanes/edge; lane (eslot*16+q) owns ch 8q..8q+7. half2 logit AND half2
// accumulation (den stays fp32); final per-node epilogue converts once.
__device__ __forceinline__ float edge_logit(uint4 raw,
                                            const __half2* xrh,
                                            const __half2* a6,
                                            const __half2* a4) {
    __half2 h0 = *(__half2*)&raw.x, h1 = *(__half2*)&raw.y;
    __half2 h2 = *(__half2*)&raw.z, h3 = *(__half2*)&raw.w;
    __half2 m0 = __hadd2(h0, xrh[0]);
    __half2 m1 = __hadd2(h1, xrh[1]);
    __half2 m2 = __hadd2(h2, xrh[2]);
    __half2 m3 = __hadd2(h3, xrh[3]);
    unsigned b0 = (*(unsigned*)&m0) & 0x7FFF7FFFu;   // |m| on the ALU pipe
    unsigned b1 = (*(unsigned*)&m1) & 0x7FFF7FFFu;
    unsigned b2 = (*(unsigned*)&m2) & 0x7FFF7FFFu;
    unsigned b3 = (*(unsigned*)&m3) & 0x7FFF7FFFu;
    __half2 t0 = __hmul2(a4[0], *(__half2*)&b0);
    t0 = __hfma2(a6[0], m0, t0);
    t0 = __hfma2(a4[1], *(__half2*)&b1, t0);
    t0 = __hfma2(a6[1], m1, t0);
    __half2 t1 = __hmul2(a4[2], *(__half2*)&b2);
    t1 = __hfma2(a6[2], m2, t1);
    t1 = __hfma2(a4[3], *(__half2*)&b3, t1);
    t1 = __hfma2(a6[3], m3, t1);
    float2 tf = __half22float2(__hadd2(t0, t1));
    return tf.x + tf.y;
}

__device__ __forceinline__ void edge_acc_h(uint4 raw, __half2 exh, __half2* hacc) {
    hacc[0] = __hfma2(exh, *(__half2*)&raw.x, hacc[0]);
    hacc[1] = __hfma2(exh, *(__half2*)&raw.y, hacc[1]);
    hacc[2] = __hfma2(exh, *(__half2*)&raw.z, hacc[2]);
    hacc[3] = __hfma2(exh, *(__half2*)&raw.w, hacc[3]);
}

__global__ void __launch_bounds__(256)
gat_main_kernel(const float* __restrict__ att,
                const float* __restrict__ bias,
                const int* __restrict__ batch,
                float* __restrict__ pooled, int n) {
    __shared__ int pbuf[HD];
    __shared__ int bmn, bmx;
    int tid = threadIdx.x;
    if (tid < HD) pbuf[tid] = 0;
    if (tid == 0) { bmn = 1 << 30; bmx = -1; }
    __syncthreads();

    int gw    = (blockIdx.x * blockDim.x + tid) >> 5;
    int lane  = tid & 31;
    int q     = lane & 15;      // channel-group: ch 8q..8q+7
    int eslot = lane >> 4;      // which edge of the pair
    bool active = (gw < n);
    float o[8] = {0, 0, 0, 0, 0, 0, 0, 0};
    int b = 0;

    if (active) {
        int i = gw;
        uint4 xr_raw = __ldg((const uint4*)g_xr16 + i * 16 + q);
        __half2 xrh[4] = { *(__half2*)&xr_raw.x, *(__half2*)&xr_raw.y,
                           *(__half2*)&xr_raw.z, *(__half2*)&xr_raw.w };
        float4 avA = ((const float4*)att)[q * 2];
        float4 avB = ((const float4*)att)[q * 2 + 1];
        __half2 a6[4] = { __floats2half2_rn(0.6f * avA.x, 0.6f * avA.y),
                          __floats2half2_rn(0.6f * avA.z, 0.6f * avA.w),
                          __floats2half2_rn(0.6f * avB.x, 0.6f * avB.y),
                          __floats2half2_rn(0.6f * avB.z, 0.6f * avB.w) };
        __half2 a4[4] = { __floats2half2_rn(0.4f * avA.x, 0.4f * avA.y),
                          __floats2half2_rn(0.4f * avA.z, 0.4f * avA.w),
                          __floats2half2_rn(0.4f * avB.x, 0.4f * avB.y),
                          __floats2half2_rn(0.4f * avB.z, 0.4f * avB.w) };

        __half2 hacc[4];
        __half2 hz = __float2half2_rn(0.0f);
        hacc[0] = hz; hacc[1] = hz; hacc[2] = hz; hacc[3] = hz;
        float den = 0.0f;

        int s0 = i << 7;                    // bucket base
        int s1 = s0 + g_cnt[i];             // bucket end (deg incl. self loop)
        int base = s0;
        for (; base + 4 <= s1; base += 4) {          // 4 edges, 2 LDG.128 in flight
            int j0 = __ldg(&g_psrc[base + eslot]);
            int j1 = __ldg(&g_psrc[base + 2 + eslot]);
            uint4 r0 = __ldg((const uint4*)g_xl16 + j0 * 16 + q);
            uint4 r1 = __ldg((const uint4*)g_xl16 + j1 * 16 + q);

            float sA = edge_logit(r0, xrh, a6, a4);
            float sB = edge_logit(r1, xrh, a6, a4);
            sA += __shfl_xor_sync(0xFFFFFFFFu, sA, 1);
            sB += __shfl_xor_sync(0xFFFFFFFFu, sB, 1);
            sA += __shfl_xor_sync(0xFFFFFFFFu, sA, 2);
            sB += __shfl_xor_sync(0xFFFFFFFFu, sB, 2);

            float eA = __expf(sA);
            float eB = __expf(sB);
            den += eA + eB;
            edge_acc_h(r0, __float2half2_rn(eA), hacc);
            edge_acc_h(r1, __float2half2_rn(eB), hacc);
        }
        for (; base < s1; base += 2) {               // masked tail pair
            int ei = base + eslot;
            int j = __ldg(&g_psrc[(ei < s1) ? ei : (s1 - 1)]);
            uint4 r = __ldg((const uint4*)g_xl16 + j * 16 + q);
            float s = edge_logit(r, xrh, a6, a4);
            s += __shfl_xor_sync(0xFFFFFFFFu, s, 1);
            s += __shfl_xor_sync(0xFFFFFFFFu, s, 2);
            float ex = (ei < s1) ? __expf(s) : 0.0f;
            den += ex;
            edge_acc_h(r, __float2half2_rn(ex), hacc);
        }

        // merge the two 16-lane halves (per-head den, per-channel acc)
        den += __shfl_xor_sync(0xFFFFFFFFu, den, 16);
#pragma unroll
        for (int t = 0; t < 4; t++) {
            unsigned u = __shfl_xor_sync(0xFFFFFFFFu, *(unsigned*)&hacc[t], 16);
            hacc[t] = __hadd2(hacc[t], *(__half2*)&u);
        }

        float inv = 1.0f / den;
        float4 bvA = ((const float4*)bias)[q * 2];
        float4 bvB = ((const float4*)bias)[q * 2 + 1];
        float2 f0 = __half22float2(hacc[0]);
        float2 f1 = __half22float2(hacc[1]);
        float2 f2 = __half22float2(hacc[2]);
        float2 f3 = __half22float2(hacc[3]);
        o[0] = fmaxf(fmaf(f0.x, inv, bvA.x), 0.0f);
        o[1] = fmaxf(fmaf(f0.y, inv, bvA.y), 0.0f);
        o[2] = fmaxf(fmaf(f1.x, inv, bvA.z), 0.0f);
        o[3] = fmaxf(fmaf(f1.y, inv, bvA.w), 0.0f);
        o[4] = fmaxf(fmaf(f2.x, inv, bvB.x), 0.0f);
        o[5] = fmaxf(fmaf(f2.y, inv, bvB.y), 0.0f);
        o[6] = fmaxf(fmaf(f3.x, inv, bvB.z), 0.0f);
        o[7] = fmaxf(fmaf(f3.y, inv, bvB.w), 0.0f);

        b = batch[i];
        if (lane == 0) { atomicMin(&bmn, b); atomicMax(&bmx, b); }
    }
    __syncthreads();

    if (bmn == bmx) {
        if (active && eslot == 0) {
#pragma unroll
            for (int t = 0; t < 8; t++)
                atomicMax(&pbuf[q * 8 + t], __float_as_int(o[t]));
        }
        __syncthreads();
        if (tid < HD && bmx >= 0)
            atomicMax((int*)pooled + bmx * HD + tid, pbuf[tid]);
    } else if (active && eslot == 0) {
        int* pp = (int*)pooled + b * HD + q * 8;
#pragma unroll
        for (int t = 0; t < 8; t++)
            atomicMax(pp + t, __float_as_int(o[t]));
    }
}

// ---------------- launcher ---------------------------------------------------
extern "C" void kernel_launch(void* const* d_in, const int* in_sizes, int n_in,
                              void* d_out, int out_size) {
    const float* x    = (const float*)d_in[0];
    const int*   ei   = (const int*)d_in[1];
    const int*   batch= (const int*)d_in[2];
    const float* Wl   = (const float*)d_in[3];
    const float* bl   = (const float*)d_in[4];
    const float* Wr   = (const float*)d_in[5];
    const float* br   = (const float*)d_in[6];
    const float* att  = (const float*)d_in[7];
    const float* bias = (const float*)d_in[8];
    float* out = (float*)d_out;

    int n = in_sizes[2];          // nodes
    int E = in_sizes[1] / 2;      // edges
    const int* esrc = ei;
    const int* edst = ei + E;

    static cudaStream_t s2 = nullptr;
    static cudaEvent_t eFork = nullptr, eJoin = nullptr;
    if (s2 == nullptr) {
        cudaStreamCreateWithFlags(&s2, cudaStreamNonBlocking);
        cudaEventCreateWithFlags(&eFork, cudaEventDisableTiming);
        cudaEventCreateWithFlags(&eJoin, cudaEventDisableTiming);
    }

    int gemm_smem = 2 * 128 * ASTRIDE * (int)sizeof(__half);   // ~68 KB
    cudaFuncSetAttribute(gemm_mma_kernel,
                         cudaFuncAttributeMaxDynamicSharedMemorySize, gemm_smem);

    // fork: bucket build on s2, GEMM on the captured (default) stream
    cudaEventRecord(eFork, 0);
    cudaStreamWaitEvent(s2, eFork, 0);

    int e8 = (E + 7) / 8;
    init_buckets_kernel<<<(n + 255) / 256, 256, 0, s2>>>(n);
    fill_kernel<<<(e8 + 255) / 256, 256, 0, s2>>>(esrc, edst, E);
    cudaEventRecord(eJoin, s2);

    cudaMemsetAsync(out, 0, (size_t)out_size * sizeof(float), 0);
    dim3 ggrid((n + 127) / 128, 2);
    gemm_mma_kernel<<<ggrid, 256, gemm_smem>>>(x, Wl, bl, Wr, br, n);

    // join, then fused GATv2 + pool
    cudaStreamWaitEvent(0, eJoin, 0);
    gat_main_kernel<<<(n * 32 + 255) / 256, 256>>>(att, bias, batch, out, n);
}